// round 1
// baseline (speedup 1.0000x reference)
#include <cuda_runtime.h>

// ---------------------------------------------------------------------------
// GIN regressor: N=100000 nodes, E=600000 edges, 128 dims everywhere.
//   h1 = ((x+agg(x)) @ w1a + b1a).relu() @ w1b + b1b
//   h2 = ((h1+agg(h1)) @ w2a + b2a).relu()
//   out = h2 @ (w2b @ wo) + (b2b . wo + bo)        <-- folded final GEMM
// ---------------------------------------------------------------------------

#define NODES 100000
#define DIM   128

__device__ __align__(16) float g_agg [NODES * DIM];
__device__ __align__(16) float g_bufA[NODES * DIM];
__device__ __align__(16) float g_bufB[NODES * DIM];
__device__ __align__(16) float g_wv  [DIM];
__device__ float g_cb;
__device__ int   g_eflag;   // 1 => edge_index is int64, 0 => int32

// ---------------------------------------------------------------------------
// Detect edge_index dtype: for int64 (values < 2^31), every odd 32-bit word
// of the buffer is zero. For int32 random indices that is astronomically
// unlikely across 64 samples.
// ---------------------------------------------------------------------------
__global__ void detect_kernel(const unsigned int* __restrict__ ei) {
    unsigned int orv = 0;
    for (int i = 0; i < 64; ++i) orv |= ei[2 * i + 1];
    g_eflag = (orv == 0u) ? 1 : 0;
}

// Fold w2b @ wo and b2b . wo + bo
__global__ void fold_wo(const float* __restrict__ w2b, const float* __restrict__ b2b,
                        const float* __restrict__ wo,  const float* __restrict__ bo) {
    int k = threadIdx.x;
    float s = 0.f;
#pragma unroll 8
    for (int n = 0; n < DIM; ++n) s += w2b[k * DIM + n] * wo[n];
    g_wv[k] = s;
    if (k == 0) {
        float c = bo[0];
        for (int n = 0; n < DIM; ++n) c += b2b[n] * wo[n];
        g_cb = c;
    }
}

__global__ void copy_f4(const float* __restrict__ in, float* __restrict__ out, int n4) {
    int i = blockIdx.x * blockDim.x + threadIdx.x;
    if (i < n4)
        reinterpret_cast<float4*>(out)[i] = reinterpret_cast<const float4*>(in)[i];
}

// One warp per edge; each lane moves one float4 (128 floats total) with a
// vector reduction into agg[dst].
__global__ void scatter_add(const float* __restrict__ feat, const void* __restrict__ eiv,
                            float* __restrict__ agg, int E) {
    int gid  = blockIdx.x * blockDim.x + threadIdx.x;
    int e    = gid >> 5;
    if (e >= E) return;
    int lane = gid & 31;

    long long s, d;
    if (g_eflag) {
        const long long* ei = (const long long*)eiv;
        s = __ldg(&ei[e]);
        d = __ldg(&ei[E + e]);
    } else {
        const int* ei = (const int*)eiv;
        s = __ldg(&ei[e]);
        d = __ldg(&ei[E + e]);
    }

    float4 v = *reinterpret_cast<const float4*>(feat + s * DIM + (lane << 2));
    float* dst = agg + d * DIM + (lane << 2);
    asm volatile("red.global.add.v4.f32 [%0], {%1,%2,%3,%4};"
                 :: "l"(dst), "f"(v.x), "f"(v.y), "f"(v.z), "f"(v.w)
                 : "memory");
}

// ---------------------------------------------------------------------------
// C[M,128] = op(A[M,128] @ W[128,128] + bias), op = relu or identity.
// 128x128 tile / block, 256 threads, 8x8 microtile per thread.
// K streamed in 32-wide chunks with register prefetch.
// ---------------------------------------------------------------------------
__global__ __launch_bounds__(256, 2)
void gemm128(const float* __restrict__ A, const float* __restrict__ W,
             const float* __restrict__ bias, float* __restrict__ C,
             int M, int do_relu) {
    __shared__ float As[128 * 33];   // [row][k], stride 33 (conflict-free scalar)
    __shared__ float Ws[32 * 128];   // [kk][n], natural layout (float4 friendly)

    const int t    = threadIdx.x;
    const int tr   = t >> 4;    // 0..15 -> rows tr*8 .. tr*8+7
    const int tc   = t & 15;    // 0..15 -> cols tc*8 .. tc*8+7
    const int row0 = blockIdx.x * 128;

    float4 aR[4], wR[4];

    // load chunk c (k in [c*32, c*32+32)) into registers
    auto load_chunk = [&](int c) {
#pragma unroll
        for (int it = 0; it < 4; ++it) {
            int idx  = t + it * 256;          // 0..1023
            int arow = idx >> 3;              // 0..127
            int aq   = idx & 7;               // k-quad 0..7
            int grow = row0 + arow;
            if (grow < M)
                aR[it] = *reinterpret_cast<const float4*>(A + (size_t)grow * DIM + c * 32 + aq * 4);
            else
                aR[it] = make_float4(0.f, 0.f, 0.f, 0.f);
        }
#pragma unroll
        for (int it = 0; it < 4; ++it) {
            int idx = t + it * 256;
            int wk  = idx >> 5;               // 0..31
            int wn  = idx & 31;               // n-quad 0..31
            wR[it] = *reinterpret_cast<const float4*>(W + (size_t)(c * 32 + wk) * DIM + wn * 4);
        }
    };

    float acc[8][8];
#pragma unroll
    for (int i = 0; i < 8; ++i)
#pragma unroll
        for (int j = 0; j < 8; ++j) acc[i][j] = 0.f;

    load_chunk(0);

#pragma unroll 1
    for (int c = 0; c < 4; ++c) {
        __syncthreads();
        // store prefetched chunk to smem
#pragma unroll
        for (int it = 0; it < 4; ++it) {
            int idx  = t + it * 256;
            int arow = idx >> 3;
            int aq   = idx & 7;
            float* p = &As[arow * 33 + aq * 4];
            p[0] = aR[it].x; p[1] = aR[it].y; p[2] = aR[it].z; p[3] = aR[it].w;
        }
#pragma unroll
        for (int it = 0; it < 4; ++it) {
            int idx = t + it * 256;
            int wk  = idx >> 5;
            int wn  = idx & 31;
            *reinterpret_cast<float4*>(&Ws[wk * DIM + wn * 4]) = wR[it];
        }
        __syncthreads();

        if (c < 3) load_chunk(c + 1);   // prefetch hidden behind compute

#pragma unroll 4
        for (int kk = 0; kk < 32; ++kk) {
            float a[8], b[8];
#pragma unroll
            for (int i = 0; i < 8; ++i) a[i] = As[(tr * 8 + i) * 33 + kk];
            float4 b0 = *reinterpret_cast<const float4*>(&Ws[kk * DIM + tc * 8]);
            float4 b1 = *reinterpret_cast<const float4*>(&Ws[kk * DIM + tc * 8 + 4]);
            b[0] = b0.x; b[1] = b0.y; b[2] = b0.z; b[3] = b0.w;
            b[4] = b1.x; b[5] = b1.y; b[6] = b1.z; b[7] = b1.w;
#pragma unroll
            for (int i = 0; i < 8; ++i)
#pragma unroll
                for (int j = 0; j < 8; ++j)
                    acc[i][j] = fmaf(a[i], b[j], acc[i][j]);
        }
    }

    // epilogue: bias (+ relu), vectorized stores
    float bs[8];
#pragma unroll
    for (int j = 0; j < 8; ++j) bs[j] = bias[tc * 8 + j];

#pragma unroll
    for (int i = 0; i < 8; ++i) {
        int grow = row0 + tr * 8 + i;
        if (grow < M) {
            float v[8];
#pragma unroll
            for (int j = 0; j < 8; ++j) {
                float o = acc[i][j] + bs[j];
                v[j] = do_relu ? fmaxf(o, 0.f) : o;
            }
            float4* dst = reinterpret_cast<float4*>(C + (size_t)grow * DIM + tc * 8);
            dst[0] = make_float4(v[0], v[1], v[2], v[3]);
            dst[1] = make_float4(v[4], v[5], v[6], v[7]);
        }
    }
}

// out[m] = dot(A[m,:], g_wv) + g_cb   (one warp per row)
__global__ void final_dot(const float* __restrict__ A, float* __restrict__ out, int M) {
    int gid  = blockIdx.x * blockDim.x + threadIdx.x;
    int row  = gid >> 5;
    if (row >= M) return;
    int lane = gid & 31;
    float4 a = reinterpret_cast<const float4*>(A + (size_t)row * DIM)[lane];
    float4 w = reinterpret_cast<const float4*>(g_wv)[lane];
    float s = a.x * w.x + a.y * w.y + a.z * w.z + a.w * w.w;
#pragma unroll
    for (int o = 16; o; o >>= 1) s += __shfl_xor_sync(0xffffffffu, s, o);
    if (lane == 0) out[row] = s + g_cb;
}

// ---------------------------------------------------------------------------
extern "C" void kernel_launch(void* const* d_in, const int* in_sizes, int n_in,
                              void* d_out, int out_size) {
    const float* x   = (const float*)d_in[0];
    const void*  ei  = d_in[1];
    const float* w1a = (const float*)d_in[2];
    const float* b1a = (const float*)d_in[3];
    const float* w1b = (const float*)d_in[4];
    const float* b1b = (const float*)d_in[5];
    const float* w2a = (const float*)d_in[6];
    const float* b2a = (const float*)d_in[7];
    const float* w2b = (const float*)d_in[8];
    const float* b2b = (const float*)d_in[9];
    const float* wo  = (const float*)d_in[10];
    const float* bo  = (const float*)d_in[11];
    float* out = (float*)d_out;

    const int M = in_sizes[0] / DIM;     // 100000
    const int E = in_sizes[1] / 2;       // 600000

    float *agg, *bufA, *bufB;
    cudaGetSymbolAddress((void**)&agg,  g_agg);
    cudaGetSymbolAddress((void**)&bufA, g_bufA);
    cudaGetSymbolAddress((void**)&bufB, g_bufB);

    const int n4         = M * (DIM / 4);
    const int copyBlocks = (n4 + 255) / 256;
    const int scatBlocks = (int)(((long long)E * 32 + 255) / 256);
    const int gemmBlocks = (M + 127) / 128;
    const int finBlocks  = (int)(((long long)M * 32 + 255) / 256);

    detect_kernel<<<1, 1>>>((const unsigned int*)ei);
    fold_wo<<<1, 128>>>(w2b, b2b, wo, bo);

    // layer 1
    copy_f4    <<<copyBlocks, 256>>>(x, agg, n4);
    scatter_add<<<scatBlocks, 256>>>(x, ei, agg, E);
    gemm128    <<<gemmBlocks, 256>>>(agg,  w1a, b1a, bufA, M, 1);
    gemm128    <<<gemmBlocks, 256>>>(bufA, w1b, b1b, bufB, M, 0);

    // layer 2
    copy_f4    <<<copyBlocks, 256>>>(bufB, agg, n4);
    scatter_add<<<scatBlocks, 256>>>(bufB, ei, agg, E);
    gemm128    <<<gemmBlocks, 256>>>(agg,  w2a, b2a, bufA, M, 1);

    // folded head
    final_dot  <<<finBlocks, 256>>>(bufA, out, M);
}

// round 3
// speedup vs baseline: 1.1289x; 1.1289x over previous
#include <cuda_runtime.h>

// ---------------------------------------------------------------------------
// GIN regressor (sm_103): HMMA mma.sync bf16 3-pass split GEMMs + CSR gather.
//   agg1 = x + segsum(x);   h1 = relu(agg1@w1a+b1a)@w1b+b1b   (fully fused)
//   agg2 = h1 + segsum(h1); out = relu(agg2@w2a+b2a)@(w2b@wo) + (b2b.wo+bo)
// ---------------------------------------------------------------------------

#define NODES 100000
#define EMAX  600000
#define DIM   128

__device__ __align__(16) float g_agg[NODES * DIM];
__device__ __align__(16) float g_h1 [NODES * DIM];
// per weight: hi[128*144] then lo[128*144] ushort (fragment-permuted, padded)
__device__ __align__(16) unsigned short g_wblob[3 * 2 * 128 * 144];
__device__ __align__(16) float g_wv[DIM];
__device__ float g_cb;
__device__ int   g_eflag;
__device__ int   g_cnt[NODES];
__device__ int   g_rowp[NODES + 1];
__device__ int   g_cursor[NODES];
__device__ int   g_srcs[EMAX];

// ------------------------------ helpers ------------------------------------
__device__ __forceinline__ unsigned smem_u32(const void* p) {
    unsigned a;
    asm("{ .reg .u64 t; cvta.to.shared.u64 t, %1; cvt.u32.u64 %0, t; }"
        : "=r"(a) : "l"(p));
    return a;
}
__device__ __forceinline__ void ldm4(unsigned* r, unsigned addr) {
    asm ("ldmatrix.sync.aligned.m8n8.x4.shared.b16 {%0,%1,%2,%3}, [%4];"
         : "=r"(r[0]), "=r"(r[1]), "=r"(r[2]), "=r"(r[3]) : "r"(addr));
}
__device__ __forceinline__ uint2 lds64(unsigned addr) {
    uint2 v;
    asm ("ld.shared.v2.u32 {%0,%1}, [%2];" : "=r"(v.x), "=r"(v.y) : "r"(addr));
    return v;
}
__device__ __forceinline__ void mma_bf(float* c, const unsigned* a, uint2 b) {
    asm ("mma.sync.aligned.m16n8k16.row.col.f32.bf16.bf16.f32 "
         "{%0,%1,%2,%3}, {%4,%5,%6,%7}, {%8,%9}, {%0,%1,%2,%3};"
         : "+f"(c[0]), "+f"(c[1]), "+f"(c[2]), "+f"(c[3])
         : "r"(a[0]), "r"(a[1]), "r"(a[2]), "r"(a[3]), "r"(b.x), "r"(b.y));
}
__device__ __forceinline__ unsigned short f2bf(float a) {
    unsigned u = __float_as_uint(a);
    return (unsigned short)((u + 0x7FFFu + ((u >> 16) & 1u)) >> 16);
}
__device__ __forceinline__ void split_bf16(float a, unsigned short& hi, unsigned short& lo) {
    hi = f2bf(a);
    lo = f2bf(a - __uint_as_float(((unsigned)hi) << 16));
}

// strides (elements)
#define AS_STRIDE 136           // A tile rows (272 B) — conflict-free ldmatrix
#define WS_STRIDE 144           // W rows (288 B)     — conflict-free LDS.64
#define W_HALF    (128 * WS_STRIDE)             // ushort count per hi or lo
#define W_PAIR_B  (2 * W_HALF * 2)              // bytes per weight (hi+lo) = 73728

// smem offsets (bytes)
#define OFF_AHI 0
#define OFF_ALO (128 * AS_STRIDE * 2)           // 34816
#define OFF_W1  (2 * 128 * AS_STRIDE * 2)       // 69632
#define OFF_W2  (OFF_W1 + W_PAIR_B)             // 143360
#define SMEM1   (OFF_W2 + W_PAIR_B)             // 217088
#define SMEM2   (OFF_W1 + W_PAIR_B)             // 143360

// ------------------------------ small kernels ------------------------------
__global__ void detect_kernel(const unsigned int* __restrict__ ei) {
    unsigned orv = 0;
    for (int i = 0; i < 64; ++i) orv |= ei[2 * i + 1];
    g_eflag = (orv == 0u) ? 1 : 0;
}

__global__ void fold_wo(const float* __restrict__ w2b, const float* __restrict__ b2b,
                        const float* __restrict__ wo,  const float* __restrict__ bo) {
    int k = threadIdx.x;
    float s = 0.f;
#pragma unroll 8
    for (int n = 0; n < DIM; ++n) s += w2b[k * DIM + n] * wo[n];
    g_wv[k] = s;
    if (k == 0) {
        float c = bo[0];
        for (int n = 0; n < DIM; ++n) c += b2b[n] * wo[n];
        g_cb = c;
    }
}

// W[k][n] -> Wt[n][k] bf16 hi/lo, k fragment-permuted within 16-chunks:
// stored pos p=4t+2b+j  <->  k_in_chunk = 2t + 8b + j   (t=0..3, b,j=0..1)
__global__ void prep_w(const float* __restrict__ w, int slot) {
    unsigned short* hiB = g_wblob + (size_t)slot * 2 * W_HALF;
    unsigned short* loB = hiB + W_HALF;
    for (int i = blockIdx.x * blockDim.x + threadIdx.x; i < W_HALF;
         i += gridDim.x * blockDim.x) {
        int n  = i / WS_STRIDE;
        int kp = i % WS_STRIDE;
        if (kp >= 128) { hiB[i] = 0; loB[i] = 0; continue; }
        int chunk = kp >> 4, p = kp & 15;
        int t = p >> 2, b = (p >> 1) & 1, j = p & 1;
        int k = chunk * 16 + 2 * t + 8 * b + j;
        unsigned short h, l;
        split_bf16(w[k * DIM + n], h, l);
        hiB[i] = h; loB[i] = l;
    }
}

__global__ void hist_kernel(const void* __restrict__ eiv, int E) {
    int e = blockIdx.x * blockDim.x + threadIdx.x;
    if (e >= E) return;
    int d = g_eflag ? (int)((const long long*)eiv)[E + e]
                    : ((const int*)eiv)[E + e];
    atomicAdd(&g_cnt[d], 1);
}

__global__ void scan_kernel(int n) {
    __shared__ int part[1024];
    int t = threadIdx.x;
    int per = (n + 1023) / 1024;
    int b = t * per, e = min(b + per, n);
    int s = 0;
    for (int i = b; i < e; ++i) s += g_cnt[i];
    part[t] = s;
    __syncthreads();
    for (int d = 1; d < 1024; d <<= 1) {
        int v = (t >= d) ? part[t - d] : 0;
        __syncthreads();
        part[t] += v;
        __syncthreads();
    }
    int run = part[t] - s;
    for (int i = b; i < e; ++i) {
        g_rowp[i] = run; g_cursor[i] = run;
        run += g_cnt[i];
    }
    if (b < n && e == n) g_rowp[n] = run;
}

__global__ void fill_kernel(const void* __restrict__ eiv, int E) {
    int e = blockIdx.x * blockDim.x + threadIdx.x;
    if (e >= E) return;
    int s, d;
    if (g_eflag) {
        const long long* ei = (const long long*)eiv;
        s = (int)ei[e]; d = (int)ei[E + e];
    } else {
        const int* ei = (const int*)eiv;
        s = ei[e]; d = ei[E + e];
    }
    int pos = atomicAdd(&g_cursor[d], 1);
    g_srcs[pos] = s;
}

// agg[v] = feat[v] + sum_{e in CSR(v)} feat[src(e)]   (one warp per node)
__global__ void gather_kernel(const float* __restrict__ feat, float* __restrict__ agg, int n) {
    int g = blockIdx.x * blockDim.x + threadIdx.x;
    int v = g >> 5;
    if (v >= n) return;
    int lane = g & 31;
    float4 acc = ((const float4*)(feat + (size_t)v * DIM))[lane];
    int s0 = __ldg(&g_rowp[v]), s1 = __ldg(&g_rowp[v + 1]);
    for (int e = s0; e < s1; ++e) {
        int s = __ldg(&g_srcs[e]);
        float4 x = ((const float4*)(feat + (size_t)s * DIM))[lane];
        acc.x += x.x; acc.y += x.y; acc.z += x.z; acc.w += x.w;
    }
    ((float4*)(agg + (size_t)v * DIM))[lane] = acc;
}

// ----------------------------- shared device code ---------------------------
// load 128x128 fp32 tile -> bf16 hi/lo row-major (stride AS_STRIDE) in smem
__device__ __forceinline__ void load_a_tile(const float* __restrict__ A, int row0, int M,
                                            char* dsm) {
    int t = threadIdx.x;
#pragma unroll
    for (int i = 0; i < 16; ++i) {
        int idx4 = i * 256 + t;                 // 0..4095
        int r = idx4 >> 5;
        int k = (idx4 & 31) << 2;
        float4 v = make_float4(0.f, 0.f, 0.f, 0.f);
        if (row0 + r < M) v = *(const float4*)(A + (size_t)(row0 + r) * DIM + k);
        unsigned short h0, h1, h2, h3, l0, l1, l2, l3;
        split_bf16(v.x, h0, l0); split_bf16(v.y, h1, l1);
        split_bf16(v.z, h2, l2); split_bf16(v.w, h3, l3);
        unsigned off = (unsigned)(r * AS_STRIDE + k) * 2;
        *(uint2*)(dsm + OFF_AHI + off) =
            make_uint2((unsigned)h0 | ((unsigned)h1 << 16), (unsigned)h2 | ((unsigned)h3 << 16));
        *(uint2*)(dsm + OFF_ALO + off) =
            make_uint2((unsigned)l0 | ((unsigned)l1 << 16), (unsigned)l2 | ((unsigned)l3 << 16));
    }
}

__device__ __forceinline__ void copy_w(char* dsm, unsigned dstOff, int slot) {
    const uint4* src = (const uint4*)(g_wblob + (size_t)slot * 2 * W_HALF);
    uint4* dst = (uint4*)(dsm + dstOff);
    for (int i = threadIdx.x; i < W_PAIR_B / 16; i += 256) dst[i] = __ldg(&src[i]);
}

// one GEMM pass set: acc += Ah*Bh + Al*Bh + Ah*Bl   (A frags given per k-step)
__device__ __forceinline__ void gemm_step(float (*acc)[4], const unsigned* ah,
                                          const unsigned* al, unsigned bhAddr,
                                          unsigned blAddr) {
#pragma unroll
    for (int nt = 0; nt < 16; ++nt) {
        uint2 bh = lds64(bhAddr + nt * (8 * WS_STRIDE * 2));
        mma_bf(acc[nt], ah, bh);
        mma_bf(acc[nt], al, bh);
    }
#pragma unroll
    for (int nt = 0; nt < 16; ++nt) {
        uint2 bl = lds64(blAddr + nt * (8 * WS_STRIDE * 2));
        mma_bf(acc[nt], ah, bl);
    }
}

// ----------------------------- fused MLP kernels ----------------------------
__global__ __launch_bounds__(256, 1)
void mlp1_kernel(const float* __restrict__ A, const float* __restrict__ b1g,
                 const float* __restrict__ b2g, float* __restrict__ H, int M) {
    extern __shared__ char dsm[];
    __shared__ float s_b1[128], s_b2[128];

    const int t = threadIdx.x;
    const int lane = t & 31;
    const int warpRow = (t >> 5) * 16;
    const int row0 = blockIdx.x * 128;
    const unsigned smb = smem_u32(dsm);

    if (t < 128) { s_b1[t] = b1g[t]; s_b2[t] = b2g[t]; }
    copy_w(dsm, OFF_W1, 0);
    copy_w(dsm, OFF_W2, 1);
    load_a_tile(A, row0, M, dsm);
    __syncthreads();

    const unsigned aoffBase = smb + (unsigned)(warpRow + (lane & 15)) * (AS_STRIDE * 2)
                            + (unsigned)(lane >> 4) * 16;
    const unsigned lbase = (unsigned)(lane >> 2) * (WS_STRIDE * 2) + (unsigned)(lane & 3) * 8;

    // ---- GEMM1: C = agg @ w1a' ----
    float acc1[16][4];
#pragma unroll
    for (int nt = 0; nt < 16; ++nt)
#pragma unroll
        for (int j = 0; j < 4; ++j) acc1[nt][j] = 0.f;

#pragma unroll
    for (int ks = 0; ks < 8; ++ks) {
        unsigned ah[4], al[4];
        ldm4(ah, aoffBase + OFF_AHI + ks * 32);
        ldm4(al, aoffBase + OFF_ALO + ks * 32);
        gemm_step(acc1, ah, al,
                  smb + OFF_W1 + lbase + ks * 32,
                  smb + OFF_W1 + W_HALF * 2 + lbase + ks * 32);
    }

    // ---- in-register epilogue1: T1 = relu(C + b1a), repack as A-fragments ----
    // C frag of n-tiles (2ks, 2ks+1) == A frag (m16k16) for k-step ks.
    unsigned a2h[8][4], a2l[8][4];
    const int tq = lane & 3;
#pragma unroll
    for (int ks = 0; ks < 8; ++ks) {
#pragma unroll
        for (int half = 0; half < 2; ++half) {        // half=0 -> nt=2ks, 1 -> 2ks+1
            int nt = 2 * ks + half;
            int col = nt * 8 + 2 * tq;
            float v0 = fmaxf(acc1[nt][0] + s_b1[col],     0.f);
            float v1 = fmaxf(acc1[nt][1] + s_b1[col + 1], 0.f);
            float v2 = fmaxf(acc1[nt][2] + s_b1[col],     0.f);
            float v3 = fmaxf(acc1[nt][3] + s_b1[col + 1], 0.f);
            unsigned short h0, h1, h2, h3, l0, l1, l2, l3;
            split_bf16(v0, h0, l0); split_bf16(v1, h1, l1);
            split_bf16(v2, h2, l2); split_bf16(v3, h3, l3);
            a2h[ks][2 * half + 0] = (unsigned)h0 | ((unsigned)h1 << 16);
            a2h[ks][2 * half + 1] = (unsigned)h2 | ((unsigned)h3 << 16);
            a2l[ks][2 * half + 0] = (unsigned)l0 | ((unsigned)l1 << 16);
            a2l[ks][2 * half + 1] = (unsigned)l2 | ((unsigned)l3 << 16);
        }
    }

    // ---- GEMM2: C = T1 @ w1b' ----
    float acc2[16][4];
#pragma unroll
    for (int nt = 0; nt < 16; ++nt)
#pragma unroll
        for (int j = 0; j < 4; ++j) acc2[nt][j] = 0.f;

#pragma unroll
    for (int ks = 0; ks < 8; ++ks)
        gemm_step(acc2, a2h[ks], a2l[ks],
                  smb + OFF_W2 + lbase + ks * 32,
                  smb + OFF_W2 + W_HALF * 2 + lbase + ks * 32);

    // ---- epilogue2: h1 = C + b1b -> global (float2 per frag pair) ----
    const int g = lane >> 2;
    const int rA = row0 + warpRow + g;
    const int rB = rA + 8;
#pragma unroll
    for (int nt = 0; nt < 16; ++nt) {
        int col = nt * 8 + 2 * tq;
        if (rA < M)
            *(float2*)(H + (size_t)rA * DIM + col) =
                make_float2(acc2[nt][0] + s_b2[col], acc2[nt][1] + s_b2[col + 1]);
        if (rB < M)
            *(float2*)(H + (size_t)rB * DIM + col) =
                make_float2(acc2[nt][2] + s_b2[col], acc2[nt][3] + s_b2[col + 1]);
    }
}

__global__ __launch_bounds__(256, 1)
void mlp2_kernel(const float* __restrict__ A, const float* __restrict__ bag,
                 float* __restrict__ out, int M) {
    extern __shared__ char dsm[];
    __shared__ float s_b[128], s_wv[128];

    const int t = threadIdx.x;
    const int lane = t & 31;
    const int warpRow = (t >> 5) * 16;
    const int row0 = blockIdx.x * 128;
    const unsigned smb = smem_u32(dsm);

    if (t < 128) { s_b[t] = bag[t]; s_wv[t] = g_wv[t]; }
    copy_w(dsm, OFF_W1, 2);
    load_a_tile(A, row0, M, dsm);
    __syncthreads();

    const unsigned aoffBase = smb + (unsigned)(warpRow + (lane & 15)) * (AS_STRIDE * 2)
                            + (unsigned)(lane >> 4) * 16;
    const unsigned lbase = (unsigned)(lane >> 2) * (WS_STRIDE * 2) + (unsigned)(lane & 3) * 8;

    float acc[16][4];
#pragma unroll
    for (int nt = 0; nt < 16; ++nt)
#pragma unroll
        for (int j = 0; j < 4; ++j) acc[nt][j] = 0.f;

#pragma unroll
    for (int ks = 0; ks < 8; ++ks) {
        unsigned ah[4], al[4];
        ldm4(ah, aoffBase + OFF_AHI + ks * 32);
        ldm4(al, aoffBase + OFF_ALO + ks * 32);
        gemm_step(acc, ah, al,
                  smb + OFF_W1 + lbase + ks * 32,
                  smb + OFF_W1 + W_HALF * 2 + lbase + ks * 32);
    }

    // fused head: out[row] = sum_col relu(C+b)*wv + cb
    const int tq = lane & 3;
    float pA = 0.f, pB = 0.f;
#pragma unroll
    for (int nt = 0; nt < 16; ++nt) {
        int col = nt * 8 + 2 * tq;
        float w0 = s_wv[col], w1 = s_wv[col + 1];
        float b0 = s_b[col],  b1 = s_b[col + 1];
        pA += fmaxf(acc[nt][0] + b0, 0.f) * w0 + fmaxf(acc[nt][1] + b1, 0.f) * w1;
        pB += fmaxf(acc[nt][2] + b0, 0.f) * w0 + fmaxf(acc[nt][3] + b1, 0.f) * w1;
    }
    pA += __shfl_xor_sync(0xffffffffu, pA, 1);
    pA += __shfl_xor_sync(0xffffffffu, pA, 2);
    pB += __shfl_xor_sync(0xffffffffu, pB, 1);
    pB += __shfl_xor_sync(0xffffffffu, pB, 2);
    if (tq == 0) {
        int rA = row0 + warpRow + (lane >> 2);
        if (rA < M)     out[rA]     = pA + g_cb;
        if (rA + 8 < M) out[rA + 8] = pB + g_cb;
    }
}

// ---------------------------------------------------------------------------
extern "C" void kernel_launch(void* const* d_in, const int* in_sizes, int n_in,
                              void* d_out, int out_size) {
    const float* x   = (const float*)d_in[0];
    const void*  ei  = d_in[1];
    const float* w1a = (const float*)d_in[2];
    const float* b1a = (const float*)d_in[3];
    const float* w1b = (const float*)d_in[4];
    const float* b1b = (const float*)d_in[5];
    const float* w2a = (const float*)d_in[6];
    const float* b2a = (const float*)d_in[7];
    const float* w2b = (const float*)d_in[8];
    const float* b2b = (const float*)d_in[9];
    const float* wo  = (const float*)d_in[10];
    const float* bo  = (const float*)d_in[11];
    float* out = (float*)d_out;

    const int M = in_sizes[0] / DIM;   // 100000
    const int E = in_sizes[1] / 2;     // 600000

    float *agg, *h1;
    int *cnt;
    cudaGetSymbolAddress((void**)&agg, g_agg);
    cudaGetSymbolAddress((void**)&h1,  g_h1);
    cudaGetSymbolAddress((void**)&cnt, g_cnt);

    cudaFuncSetAttribute(mlp1_kernel, cudaFuncAttributeMaxDynamicSharedMemorySize, SMEM1);
    cudaFuncSetAttribute(mlp2_kernel, cudaFuncAttributeMaxDynamicSharedMemorySize, SMEM2);

    const int tiles      = (M + 127) / 128;
    const int edgeBlocks = (E + 255) / 256;
    const int gathBlocks = (int)(((long long)M * 32 + 255) / 256);

    detect_kernel<<<1, 1>>>((const unsigned int*)ei);
    fold_wo<<<1, 128>>>(w2b, b2b, wo, bo);
    prep_w<<<18, 1024>>>(w1a, 0);
    prep_w<<<18, 1024>>>(w1b, 1);
    prep_w<<<18, 1024>>>(w2a, 2);

    // CSR build (reused by both layers)
    cudaMemsetAsync(cnt, 0, (size_t)M * sizeof(int));
    hist_kernel<<<edgeBlocks, 256>>>(ei, E);
    scan_kernel<<<1, 1024>>>(M);
    fill_kernel<<<edgeBlocks, 256>>>(ei, E);

    // layer 1 (fully fused MLP)
    gather_kernel<<<gathBlocks, 256>>>(x, agg, M);
    mlp1_kernel<<<tiles, 256, SMEM1>>>(agg, b1a, b1b, h1, M);

    // layer 2 + folded head
    gather_kernel<<<gathBlocks, 256>>>(h1, agg, M);
    mlp2_kernel<<<tiles, 256, SMEM2>>>(agg, b2a, out, M);
}

// round 5
// speedup vs baseline: 1.1502x; 1.0189x over previous
#include <cuda_runtime.h>

// ---------------------------------------------------------------------------
// GIN regressor (sm_103): HMMA bf16 3-pass split GEMMs + CSR gather.
// Launch order fixed so ncu (-s 5) profiles mlp1_kernel.
// R5 fix: ldm4 must be volatile+memory — GEMM2 re-reads SMEM that epilogue1
// overwrote; pure asm let nvcc CSE the reload against GEMM1's loads.
// ---------------------------------------------------------------------------

#define NODES 100000
#define EMAX  600000
#define DIM   128

__device__ __align__(16) float g_agg[NODES * DIM];
__device__ __align__(16) float g_h1 [NODES * DIM];
__device__ __align__(16) unsigned short g_wblob[3 * 2 * 128 * 144];
__device__ __align__(16) float g_wv[DIM];
__device__ float g_cb;
__device__ int   g_eflag;
__device__ int   g_cnt[NODES];
__device__ int   g_rowp[NODES + 1];
__device__ int   g_cursor[NODES];
__device__ int   g_srcs[EMAX];

// ------------------------------ helpers ------------------------------------
__device__ __forceinline__ unsigned smem_u32(const void* p) {
    unsigned a;
    asm("{ .reg .u64 t; cvta.to.shared.u64 t, %1; cvt.u32.u64 %0, t; }"
        : "=r"(a) : "l"(p));
    return a;
}
// volatile + memory: SMEM contents change between GEMM1 and GEMM2 reads of
// the SAME address — must not be CSE'd or reordered.
__device__ __forceinline__ void ldm4(unsigned* r, unsigned addr) {
    asm volatile("ldmatrix.sync.aligned.m8n8.x4.shared.b16 {%0,%1,%2,%3}, [%4];"
                 : "=r"(r[0]), "=r"(r[1]), "=r"(r[2]), "=r"(r[3]) : "r"(addr)
                 : "memory");
}
__device__ __forceinline__ uint2 lds64(unsigned addr) {
    uint2 v;
    asm ("ld.shared.v2.u32 {%0,%1}, [%2];" : "=r"(v.x), "=r"(v.y) : "r"(addr));
    return v;
}
__device__ __forceinline__ void sts32(unsigned addr, unsigned v) {
    asm volatile("st.shared.u32 [%0], %1;" :: "r"(addr), "r"(v) : "memory");
}
__device__ __forceinline__ void mma_bf(float* c, const unsigned* a, uint2 b) {
    asm ("mma.sync.aligned.m16n8k16.row.col.f32.bf16.bf16.f32 "
         "{%0,%1,%2,%3}, {%4,%5,%6,%7}, {%8,%9}, {%0,%1,%2,%3};"
         : "+f"(c[0]), "+f"(c[1]), "+f"(c[2]), "+f"(c[3])
         : "r"(a[0]), "r"(a[1]), "r"(a[2]), "r"(a[3]), "r"(b.x), "r"(b.y));
}
__device__ __forceinline__ unsigned short f2bf(float a) {
    unsigned u = __float_as_uint(a);
    return (unsigned short)((u + 0x7FFFu + ((u >> 16) & 1u)) >> 16);
}
__device__ __forceinline__ void split_bf16(float a, unsigned short& hi, unsigned short& lo) {
    hi = f2bf(a);
    lo = f2bf(a - __uint_as_float(((unsigned)hi) << 16));
}

#define AS_STRIDE 136
#define WS_STRIDE 144
#define W_HALF    (128 * WS_STRIDE)
#define W_PAIR_B  (2 * W_HALF * 2)

#define OFF_AHI 0
#define OFF_ALO (128 * AS_STRIDE * 2)
#define OFF_W1  (2 * 128 * AS_STRIDE * 2)
#define OFF_W2  (OFF_W1 + W_PAIR_B)
#define SMEM1   (OFF_W2 + W_PAIR_B)
#define SMEM2   (OFF_W1 + W_PAIR_B)

#define NT_STEP_B (8 * WS_STRIDE * 2)

// --------------------------- setup (launch 0) -------------------------------
__global__ void setup_kernel(const unsigned int* __restrict__ ei,
                             const float* __restrict__ w1a,
                             const float* __restrict__ w1b,
                             const float* __restrict__ w2a,
                             const float* __restrict__ w2b,
                             const float* __restrict__ b2b,
                             const float* __restrict__ wo,
                             const float* __restrict__ bo) {
    int b = blockIdx.x, t = threadIdx.x;
    if (b == 0) {
        if (t == 0) {
            unsigned orv = 0;
            for (int i = 0; i < 64; ++i) orv |= ei[2 * i + 1];
            g_eflag = (orv == 0u) ? 1 : 0;
        }
        if (t < 128) {
            float s = 0.f;
#pragma unroll 8
            for (int n = 0; n < DIM; ++n) s += w2b[t * DIM + n] * wo[n];
            g_wv[t] = s;
            if (t == 0) {
                float c = bo[0];
                for (int n = 0; n < DIM; ++n) c += b2b[n] * wo[n];
                g_cb = c;
            }
        }
    } else if (b <= 216) {
        int i = (b - 1) * 256 + t;                 // 0 .. 3*W_HALF-1
        int slot = i / W_HALF;
        int j    = i - slot * W_HALF;
        const float* w = (slot == 0) ? w1a : (slot == 1) ? w1b : w2a;
        unsigned short* hiB = g_wblob + (size_t)slot * 2 * W_HALF;
        unsigned short* loB = hiB + W_HALF;
        int n  = j / WS_STRIDE;
        int kp = j - n * WS_STRIDE;
        if (kp >= 128) { hiB[j] = 0; loB[j] = 0; }
        else {
            int chunk = kp >> 4, p = kp & 15;
            int tt = p >> 2, bb = (p >> 1) & 1, jj = p & 1;
            int k = chunk * 16 + 2 * tt + 8 * bb + jj;
            unsigned short h, l;
            split_bf16(w[k * DIM + n], h, l);
            hiB[j] = h; loB[j] = l;
        }
    } else {
        for (int i = (b - 217) * 256 + t; i < NODES; i += 39 * 256) g_cnt[i] = 0;
    }
}

// ------------------------------ CSR kernels --------------------------------
__global__ void hist_kernel(const void* __restrict__ eiv, int E) {
    int e = blockIdx.x * blockDim.x + threadIdx.x;
    if (e >= E) return;
    int d = g_eflag ? (int)((const long long*)eiv)[E + e]
                    : ((const int*)eiv)[E + e];
    atomicAdd(&g_cnt[d], 1);
}

__global__ void scan_kernel(int n) {
    __shared__ int part[1024];
    int t = threadIdx.x;
    int per = (n + 1023) / 1024;
    int b = t * per, e = min(b + per, n);
    int s = 0;
    for (int i = b; i < e; ++i) s += g_cnt[i];
    part[t] = s;
    __syncthreads();
    for (int d = 1; d < 1024; d <<= 1) {
        int v = (t >= d) ? part[t - d] : 0;
        __syncthreads();
        part[t] += v;
        __syncthreads();
    }
    int run = part[t] - s;
    for (int i = b; i < e; ++i) {
        g_rowp[i] = run; g_cursor[i] = run;
        run += g_cnt[i];
    }
    if (b < n && e == n) g_rowp[n] = run;
}

__global__ void fill_kernel(const void* __restrict__ eiv, int E) {
    int e = blockIdx.x * blockDim.x + threadIdx.x;
    if (e >= E) return;
    int s, d;
    if (g_eflag) {
        const long long* ei = (const long long*)eiv;
        s = (int)ei[e]; d = (int)ei[E + e];
    } else {
        const int* ei = (const int*)eiv;
        s = ei[e]; d = ei[E + e];
    }
    int pos = atomicAdd(&g_cursor[d], 1);
    g_srcs[pos] = s;
}

__global__ void gather_kernel(const float* __restrict__ feat, float* __restrict__ agg, int n) {
    int g = blockIdx.x * blockDim.x + threadIdx.x;
    int v = g >> 5;
    if (v >= n) return;
    int lane = g & 31;
    float4 acc = ((const float4*)(feat + (size_t)v * DIM))[lane];
    int s0 = __ldg(&g_rowp[v]), s1 = __ldg(&g_rowp[v + 1]);
    for (int e = s0; e < s1; ++e) {
        int s = __ldg(&g_srcs[e]);
        float4 x = ((const float4*)(feat + (size_t)s * DIM))[lane];
        acc.x += x.x; acc.y += x.y; acc.z += x.z; acc.w += x.w;
    }
    ((float4*)(agg + (size_t)v * DIM))[lane] = acc;
}

// ----------------------------- shared MLP code ------------------------------
__device__ __forceinline__ void load_a_tile(const float* __restrict__ A, int row0, int M,
                                            char* dsm, int nthreads) {
    int t = threadIdx.x;
    for (int idx4 = t; idx4 < 4096; idx4 += nthreads) {
        int r = idx4 >> 5;
        int k = (idx4 & 31) << 2;
        float4 v = make_float4(0.f, 0.f, 0.f, 0.f);
        if (row0 + r < M) v = *(const float4*)(A + (size_t)(row0 + r) * DIM + k);
        unsigned short h0, h1, h2, h3, l0, l1, l2, l3;
        split_bf16(v.x, h0, l0); split_bf16(v.y, h1, l1);
        split_bf16(v.z, h2, l2); split_bf16(v.w, h3, l3);
        unsigned off = (unsigned)(r * AS_STRIDE + k) * 2;
        *(uint2*)(dsm + OFF_AHI + off) =
            make_uint2((unsigned)h0 | ((unsigned)h1 << 16), (unsigned)h2 | ((unsigned)h3 << 16));
        *(uint2*)(dsm + OFF_ALO + off) =
            make_uint2((unsigned)l0 | ((unsigned)l1 << 16), (unsigned)l2 | ((unsigned)l3 << 16));
    }
}

__device__ __forceinline__ void copy_w(char* dsm, unsigned dstOff, int slot, int nthreads) {
    const uint4* src = (const uint4*)(g_wblob + (size_t)slot * 2 * W_HALF);
    uint4* dst = (uint4*)(dsm + dstOff);
    for (int i = threadIdx.x; i < W_PAIR_B / 16; i += nthreads) dst[i] = __ldg(&src[i]);
}

// acc[8][4] over 8 n-tiles: acc += Ah*Bh + Al*Bh + Ah*Bl
__device__ __forceinline__ void gemm_half(float (*acc)[4], const unsigned* ah,
                                          const unsigned* al, unsigned bhAddr,
                                          unsigned blAddr) {
#pragma unroll
    for (int nt = 0; nt < 8; ++nt) {
        uint2 bh = lds64(bhAddr + nt * NT_STEP_B);
        mma_bf(acc[nt], ah, bh);
        mma_bf(acc[nt], al, bh);
    }
#pragma unroll
    for (int nt = 0; nt < 8; ++nt) {
        uint2 bl = lds64(blAddr + nt * NT_STEP_B);
        mma_bf(acc[nt], ah, bl);
    }
}

// ----------------------------- fused MLP kernels ----------------------------
__global__ __launch_bounds__(512, 1)
void mlp1_kernel(const float* __restrict__ A, const float* __restrict__ b1g,
                 const float* __restrict__ b2g, float* __restrict__ H, int M) {
    extern __shared__ char dsm[];
    __shared__ float s_b1[128], s_b2[128];

    const int t = threadIdx.x;
    const int lane = t & 31;
    const int warp = t >> 5;              // 0..15
    const int wr   = (warp & 7) * 16;     // row offset
    const int nh   = warp >> 3;           // n-half 0/1
    const int ntB  = nh * 8;              // n-tile base
    const int row0 = blockIdx.x * 128;
    const unsigned smb = smem_u32(dsm);

    if (t < 128) { s_b1[t] = b1g[t]; s_b2[t] = b2g[t]; }
    copy_w(dsm, OFF_W1, 0, 512);
    copy_w(dsm, OFF_W2, 1, 512);
    load_a_tile(A, row0, M, dsm, 512);
    __syncthreads();

    const unsigned aoffBase = smb + (unsigned)(wr + (lane & 15)) * (AS_STRIDE * 2)
                            + (unsigned)(lane >> 4) * 16;
    const unsigned lbase = (unsigned)(lane >> 2) * (WS_STRIDE * 2)
                         + (unsigned)(lane & 3) * 8
                         + (unsigned)ntB * NT_STEP_B;

    // ---- GEMM1 ----
    float acc1[8][4];
#pragma unroll
    for (int nt = 0; nt < 8; ++nt)
#pragma unroll
        for (int j = 0; j < 4; ++j) acc1[nt][j] = 0.f;

#pragma unroll
    for (int ks = 0; ks < 8; ++ks) {
        unsigned ah[4], al[4];
        ldm4(ah, aoffBase + OFF_AHI + ks * 32);
        ldm4(al, aoffBase + OFF_ALO + ks * 32);
        gemm_half(acc1, ah, al,
                  smb + OFF_W1 + lbase + ks * 32,
                  smb + OFF_W1 + W_HALF * 2 + lbase + ks * 32);
    }
    __syncthreads();   // all GEMM1 A-reads done before we overwrite A buffers

    // ---- epilogue1: T1 = relu(C+b1a) -> packed bf16 back into A buffers ----
    const int tq = lane & 3;
    const int g  = lane >> 2;
#pragma unroll
    for (int nt = 0; nt < 8; ++nt) {
        int col = (ntB + nt) * 8 + 2 * tq;
        float v0 = fmaxf(acc1[nt][0] + s_b1[col],     0.f);
        float v1 = fmaxf(acc1[nt][1] + s_b1[col + 1], 0.f);
        float v2 = fmaxf(acc1[nt][2] + s_b1[col],     0.f);
        float v3 = fmaxf(acc1[nt][3] + s_b1[col + 1], 0.f);
        unsigned short h0, h1, h2, h3, l0, l1, l2, l3;
        split_bf16(v0, h0, l0); split_bf16(v1, h1, l1);
        split_bf16(v2, h2, l2); split_bf16(v3, h3, l3);
        unsigned offA = (unsigned)((wr + g) * AS_STRIDE + col) * 2;
        unsigned offB = (unsigned)((wr + g + 8) * AS_STRIDE + col) * 2;
        sts32(smb + OFF_AHI + offA, (unsigned)h0 | ((unsigned)h1 << 16));
        sts32(smb + OFF_AHI + offB, (unsigned)h2 | ((unsigned)h3 << 16));
        sts32(smb + OFF_ALO + offA, (unsigned)l0 | ((unsigned)l1 << 16));
        sts32(smb + OFF_ALO + offB, (unsigned)l2 | ((unsigned)l3 << 16));
    }
    __syncthreads();

    // ---- GEMM2 ----
    float acc2[8][4];
#pragma unroll
    for (int nt = 0; nt < 8; ++nt)
#pragma unroll
        for (int j = 0; j < 4; ++j) acc2[nt][j] = 0.f;

#pragma unroll
    for (int ks = 0; ks < 8; ++ks) {
        unsigned ah[4], al[4];
        ldm4(ah, aoffBase + OFF_AHI + ks * 32);
        ldm4(al, aoffBase + OFF_ALO + ks * 32);
        gemm_half(acc2, ah, al,
                  smb + OFF_W2 + lbase + ks * 32,
                  smb + OFF_W2 + W_HALF * 2 + lbase + ks * 32);
    }

    // ---- epilogue2: h1 = C + b1b -> global ----
    const int rA = row0 + wr + g;
    const int rB = rA + 8;
#pragma unroll
    for (int nt = 0; nt < 8; ++nt) {
        int col = (ntB + nt) * 8 + 2 * tq;
        if (rA < M)
            *(float2*)(H + (size_t)rA * DIM + col) =
                make_float2(acc2[nt][0] + s_b2[col], acc2[nt][1] + s_b2[col + 1]);
        if (rB < M)
            *(float2*)(H + (size_t)rB * DIM + col) =
                make_float2(acc2[nt][2] + s_b2[col], acc2[nt][3] + s_b2[col + 1]);
    }
}

__global__ __launch_bounds__(512, 1)
void mlp2_kernel(const float* __restrict__ A, const float* __restrict__ bag,
                 float* __restrict__ out, int M) {
    extern __shared__ char dsm[];
    __shared__ float s_b[128], s_wv[128], s_part[128];

    const int t = threadIdx.x;
    const int lane = t & 31;
    const int warp = t >> 5;
    const int wr   = (warp & 7) * 16;
    const int ntB  = (warp >> 3) * 8;
    const int row0 = blockIdx.x * 128;
    const unsigned smb = smem_u32(dsm);

    if (t < 128) { s_b[t] = bag[t]; s_wv[t] = g_wv[t]; s_part[t] = 0.f; }
    copy_w(dsm, OFF_W1, 2, 512);
    load_a_tile(A, row0, M, dsm, 512);
    __syncthreads();

    const unsigned aoffBase = smb + (unsigned)(wr + (lane & 15)) * (AS_STRIDE * 2)
                            + (unsigned)(lane >> 4) * 16;
    const unsigned lbase = (unsigned)(lane >> 2) * (WS_STRIDE * 2)
                         + (unsigned)(lane & 3) * 8
                         + (unsigned)ntB * NT_STEP_B;

    float acc[8][4];
#pragma unroll
    for (int nt = 0; nt < 8; ++nt)
#pragma unroll
        for (int j = 0; j < 4; ++j) acc[nt][j] = 0.f;

#pragma unroll
    for (int ks = 0; ks < 8; ++ks) {
        unsigned ah[4], al[4];
        ldm4(ah, aoffBase + OFF_AHI + ks * 32);
        ldm4(al, aoffBase + OFF_ALO + ks * 32);
        gemm_half(acc, ah, al,
                  smb + OFF_W1 + lbase + ks * 32,
                  smb + OFF_W1 + W_HALF * 2 + lbase + ks * 32);
    }

    // fused head: partial dot over this warp's 64 columns
    const int tq = lane & 3;
    float pA = 0.f, pB = 0.f;
#pragma unroll
    for (int nt = 0; nt < 8; ++nt) {
        int col = (ntB + nt) * 8 + 2 * tq;
        float w0 = s_wv[col], w1 = s_wv[col + 1];
        float b0 = s_b[col],  b1 = s_b[col + 1];
        pA += fmaxf(acc[nt][0] + b0, 0.f) * w0 + fmaxf(acc[nt][1] + b1, 0.f) * w1;
        pB += fmaxf(acc[nt][2] + b0, 0.f) * w0 + fmaxf(acc[nt][3] + b1, 0.f) * w1;
    }
    pA += __shfl_xor_sync(0xffffffffu, pA, 1);
    pA += __shfl_xor_sync(0xffffffffu, pA, 2);
    pB += __shfl_xor_sync(0xffffffffu, pB, 1);
    pB += __shfl_xor_sync(0xffffffffu, pB, 2);
    if (tq == 0) {
        int r = wr + (lane >> 2);
        atomicAdd(&s_part[r], pA);
        atomicAdd(&s_part[r + 8], pB);
    }
    __syncthreads();
    if (t < 128 && row0 + t < M) out[row0 + t] = s_part[t] + g_cb;
}

// ---------------------------------------------------------------------------
extern "C" void kernel_launch(void* const* d_in, const int* in_sizes, int n_in,
                              void* d_out, int out_size) {
    const float* x   = (const float*)d_in[0];
    const void*  ei  = d_in[1];
    const float* w1a = (const float*)d_in[2];
    const float* b1a = (const float*)d_in[3];
    const float* w1b = (const float*)d_in[4];
    const float* b1b = (const float*)d_in[5];
    const float* w2a = (const float*)d_in[6];
    const float* b2a = (const float*)d_in[7];
    const float* w2b = (const float*)d_in[8];
    const float* b2b = (const float*)d_in[9];
    const float* wo  = (const float*)d_in[10];
    const float* bo  = (const float*)d_in[11];
    float* out = (float*)d_out;

    const int M = in_sizes[0] / DIM;   // 100000
    const int E = in_sizes[1] / 2;     // 600000

    float *agg, *h1;
    cudaGetSymbolAddress((void**)&agg, g_agg);
    cudaGetSymbolAddress((void**)&h1,  g_h1);

    cudaFuncSetAttribute(mlp1_kernel, cudaFuncAttributeMaxDynamicSharedMemorySize, SMEM1);
    cudaFuncSetAttribute(mlp2_kernel, cudaFuncAttributeMaxDynamicSharedMemorySize, SMEM2);

    const int tiles      = (M + 127) / 128;
    const int edgeBlocks = (E + 255) / 256;
    const int gathBlocks = (int)(((long long)M * 32 + 255) / 256);

    // launch index:        0
    setup_kernel<<<256, 256>>>((const unsigned int*)ei, w1a, w1b, w2a, w2b, b2b, wo, bo);
    // CSR build:           1, 2, 3
    hist_kernel<<<edgeBlocks, 256>>>(ei, E);
    scan_kernel<<<1, 1024>>>(M);
    fill_kernel<<<edgeBlocks, 256>>>(ei, E);
    // layer 1:             4, 5   (ncu -s 5 captures mlp1_kernel)
    gather_kernel<<<gathBlocks, 256>>>(x, agg, M);
    mlp1_kernel<<<tiles, 512, SMEM1>>>(agg, b1a, b1b, h1, M);
    // layer 2 + head:      6, 7
    gather_kernel<<<gathBlocks, 256>>>(h1, agg, M);
    mlp2_kernel<<<tiles, 512, SMEM2>>>(agg, b2a, out, M);
}